// round 1
// baseline (speedup 1.0000x reference)
#include <cuda_runtime.h>

#define Dn 32
#define Ln 65536

// ---- f32x2 packed helpers (Blackwell sm_100+) ----
__device__ __forceinline__ unsigned long long pack2(float lo, float hi) {
    unsigned long long r;
    asm("mov.b64 %0, {%1, %2};" : "=l"(r) : "f"(lo), "f"(hi));
    return r;
}
__device__ __forceinline__ unsigned long long fma2(unsigned long long a,
                                                   unsigned long long b,
                                                   unsigned long long c) {
    unsigned long long d;
    asm("fma.rn.f32x2 %0, %1, %2, %3;" : "=l"(d) : "l"(a), "l"(b), "l"(c));
    return d;
}
__device__ __forceinline__ float2 unpack2(unsigned long long v) {
    float2 f;
    asm("mov.b64 {%0, %1}, %2;" : "=f"(f.x), "=f"(f.y) : "l"(v));
    return f;
}

// One thread: 8 consecutive output positions, all 4 output channels of one
// (batch, relation). Accumulators are f32x2 packed over (o0,o1) / (o2,o3) so
// the weight operand is a pre-packed LDS.64 pair and x is a (x,x) dup.
__global__ __launch_bounds__(256, 2)
void conv4x8x5_kernel(const float* __restrict__ x,
                      const float* __restrict__ k0, const float* __restrict__ k1,
                      const float* __restrict__ k2, const float* __restrict__ k3,
                      float* __restrict__ y)
{
    __shared__ unsigned long long shW[8][5][2];  // [in_ch][tap][o-pair] = (k[2op], k[2op+1])

    const int r = blockIdx.y;
    const int b = blockIdx.z;
    const float* ker = (r == 0) ? k0 : (r == 1) ? k1 : (r == 2) ? k2 : k3;

    const int t = threadIdx.x;
    if (t < 80) {
        const int op = t & 1;
        const int w  = (t >> 1) % 5;
        const int i  = t / 10;
        // kernels layout (4,8,5): ker[o][i][w] at o*40 + i*5 + w
        const float wa = ker[(2 * op)     * 40 + i * 5 + w];
        const float wb = ker[(2 * op + 1) * 40 + i * 5 + w];
        shW[i][w][op] = pack2(wa, wb);
    }
    __syncthreads();

    const int l0 = (blockIdx.x * 256 + t) * 8;

    unsigned long long acc[2][8];
    #pragma unroll
    for (int op = 0; op < 2; op++)
        #pragma unroll
        for (int p = 0; p < 8; p++)
            acc[op][p] = 0ull;  // (0.0f, 0.0f)

    const float* xb = x + ((size_t)(b * Dn + 8 * r) * Ln) + l0;

    #pragma unroll 2
    for (int i = 0; i < 8; i++) {
        const float* xc = xb + (size_t)i * Ln;

        // positions l0-2 .. l0+9 (halo = one aligned float2 each side)
        float2 lo = (l0 > 0)      ? *(const float2*)(xc - 2) : make_float2(0.f, 0.f);
        float4 m0 = *(const float4*)(xc);
        float4 m1 = *(const float4*)(xc + 4);
        float2 hi = (l0 < Ln - 8) ? *(const float2*)(xc + 8) : make_float2(0.f, 0.f);

        float xv[12];
        xv[0]  = lo.x; xv[1]  = lo.y;
        xv[2]  = m0.x; xv[3]  = m0.y; xv[4]  = m0.z; xv[5]  = m0.w;
        xv[6]  = m1.x; xv[7]  = m1.y; xv[8]  = m1.z; xv[9]  = m1.w;
        xv[10] = hi.x; xv[11] = hi.y;

        unsigned long long dup[12];
        #pragma unroll
        for (int j = 0; j < 12; j++) dup[j] = pack2(xv[j], xv[j]);

        #pragma unroll
        for (int w = 0; w < 5; w++) {
            const unsigned long long w0 = shW[i][w][0];
            const unsigned long long w1 = shW[i][w][1];
            #pragma unroll
            for (int p = 0; p < 8; p++) {
                // out[l0+p] += k[w] * x[l0+p+w-2]; xv[j] = x[l0+j-2] -> index p+w
                acc[0][p] = fma2(w0, dup[p + w], acc[0][p]);
                acc[1][p] = fma2(w1, dup[p + w], acc[1][p]);
            }
        }
    }

    // Unpack o-pairs and store 4 contiguous rows (channels 4r..4r+3)
    float res[4][8];
    #pragma unroll
    for (int op = 0; op < 2; op++)
        #pragma unroll
        for (int p = 0; p < 8; p++) {
            const float2 f = unpack2(acc[op][p]);
            res[2 * op][p]     = f.x;
            res[2 * op + 1][p] = f.y;
        }

    float* yb = y + ((size_t)(b * 16 + 4 * r) * Ln) + l0;
    #pragma unroll
    for (int o = 0; o < 4; o++) {
        float* row = yb + (size_t)o * Ln;
        *(float4*)(row)     = make_float4(res[o][0], res[o][1], res[o][2], res[o][3]);
        *(float4*)(row + 4) = make_float4(res[o][4], res[o][5], res[o][6], res[o][7]);
    }
}

extern "C" void kernel_launch(void* const* d_in, const int* in_sizes, int n_in,
                              void* d_out, int out_size)
{
    const float* x  = (const float*)d_in[0];
    const float* k0 = (const float*)d_in[1];
    const float* k1 = (const float*)d_in[2];
    const float* k2 = (const float*)d_in[3];
    const float* k3 = (const float*)d_in[4];
    float* y = (float*)d_out;

    // 8 positions/thread, 256 threads/block -> 2048 positions/block
    dim3 grid(Ln / 2048, 4, 32);  // (pos tiles, relation, batch)
    dim3 block(256);
    conv4x8x5_kernel<<<grid, block>>>(x, k0, k1, k2, k3, y);
}

// round 2
// speedup vs baseline: 1.1066x; 1.1066x over previous
#include <cuda_runtime.h>

#define Dn 32
#define Ln 65536

// All 4 relation kernels: [r][o][i][w] = 4 x 4 x 8 x 5 floats = 640
__constant__ float cW[640];

// ---- f32x2 packed helpers (Blackwell sm_100+) ----
__device__ __forceinline__ unsigned long long pack2(float lo, float hi) {
    unsigned long long r;
    asm("mov.b64 %0, {%1, %2};" : "=l"(r) : "f"(lo), "f"(hi));
    return r;
}
__device__ __forceinline__ unsigned long long fma2(unsigned long long a,
                                                   unsigned long long b,
                                                   unsigned long long c) {
    unsigned long long d;
    asm("fma.rn.f32x2 %0, %1, %2, %3;" : "=l"(d) : "l"(a), "l"(b), "l"(c));
    return d;
}
__device__ __forceinline__ float2 unpack2(unsigned long long v) {
    float2 f;
    asm("mov.b64 {%0, %1}, %2;" : "=f"(f.x), "=f"(f.y) : "l"(v));
    return f;
}

// One thread: 8 consecutive output positions, all 4 output channels of one
// (batch, relation). Accumulators are f32x2 packed over (o0,o1)/(o2,o3).
// Weights come from __constant__ with warp-uniform addresses (LDCU path),
// freeing the smem crossbar / L1tex port entirely for LDG/STG.
__global__ __launch_bounds__(256, 3)
void conv4x8x5_kernel(const float* __restrict__ x, float* __restrict__ y)
{
    const int r = blockIdx.y;
    const int b = blockIdx.z;
    const float* kr = cW + r * 160;   // [o][i][w] : o*40 + i*5 + w

    const int t  = threadIdx.x;
    const int l0 = (blockIdx.x * 256 + t) * 8;

    unsigned long long acc[2][8];
    #pragma unroll
    for (int op = 0; op < 2; op++)
        #pragma unroll
        for (int p = 0; p < 8; p++)
            acc[op][p] = 0ull;

    const float* xb = x + ((size_t)(b * Dn + 8 * r) * Ln) + l0;

    #pragma unroll 2
    for (int i = 0; i < 8; i++) {
        const float* xc = xb + (size_t)i * Ln;

        // positions l0-2 .. l0+9 (halo = one aligned float2 each side)
        float2 lo = (l0 > 0)      ? *(const float2*)(xc - 2) : make_float2(0.f, 0.f);
        float4 m0 = *(const float4*)(xc);
        float4 m1 = *(const float4*)(xc + 4);
        float2 hi = (l0 < Ln - 8) ? *(const float2*)(xc + 8) : make_float2(0.f, 0.f);

        float xv[12];
        xv[0]  = lo.x; xv[1]  = lo.y;
        xv[2]  = m0.x; xv[3]  = m0.y; xv[4]  = m0.z; xv[5]  = m0.w;
        xv[6]  = m1.x; xv[7]  = m1.y; xv[8]  = m1.z; xv[9]  = m1.w;
        xv[10] = hi.x; xv[11] = hi.y;

        unsigned long long dup[12];
        #pragma unroll
        for (int j = 0; j < 12; j++) dup[j] = pack2(xv[j], xv[j]);

        #pragma unroll
        for (int w = 0; w < 5; w++) {
            // warp-uniform constant loads -> LDCU + cheap packs, hoisted per (i,w)
            const unsigned long long w0 =
                pack2(kr[0 * 40 + i * 5 + w], kr[1 * 40 + i * 5 + w]);
            const unsigned long long w1 =
                pack2(kr[2 * 40 + i * 5 + w], kr[3 * 40 + i * 5 + w]);
            #pragma unroll
            for (int p = 0; p < 8; p++) {
                acc[0][p] = fma2(w0, dup[p + w], acc[0][p]);
                acc[1][p] = fma2(w1, dup[p + w], acc[1][p]);
            }
        }
    }

    // Unpack o-pairs and store 4 contiguous rows (channels 4r..4r+3)
    float res[4][8];
    #pragma unroll
    for (int op = 0; op < 2; op++)
        #pragma unroll
        for (int p = 0; p < 8; p++) {
            const float2 f = unpack2(acc[op][p]);
            res[2 * op][p]     = f.x;
            res[2 * op + 1][p] = f.y;
        }

    float* yb = y + ((size_t)(b * 16 + 4 * r) * Ln) + l0;
    #pragma unroll
    for (int o = 0; o < 4; o++) {
        float* row = yb + (size_t)o * Ln;
        *(float4*)(row)     = make_float4(res[o][0], res[o][1], res[o][2], res[o][3]);
        *(float4*)(row + 4) = make_float4(res[o][4], res[o][5], res[o][6], res[o][7]);
    }
}

extern "C" void kernel_launch(void* const* d_in, const int* in_sizes, int n_in,
                              void* d_out, int out_size)
{
    const float* x = (const float*)d_in[0];
    float* y = (float*)d_out;

    // Stage the 4 small kernels into constant memory (graph-capturable,
    // device-to-device, no allocation).
    for (int i = 0; i < 4; i++) {
        cudaMemcpyToSymbolAsync(cW, d_in[1 + i], 160 * sizeof(float),
                                (size_t)i * 160 * sizeof(float),
                                cudaMemcpyDeviceToDevice, 0);
    }

    // 8 positions/thread, 256 threads/block -> 2048 positions/block
    dim3 grid(Ln / 2048, 4, 32);  // (pos tiles, relation, batch)
    dim3 block(256);
    conv4x8x5_kernel<<<grid, block>>>(x, y);
}